// round 5
// baseline (speedup 1.0000x reference)
#include <cuda_runtime.h>
#include <cstdint>
#include <cstddef>

// ---------------- problem constants ----------------
#define SEQLEN 8192
#define DM     768
#define DIN    1152     // 1.5 * 768
#define DFF    3072     // 4 * 768
#define VOC    32000
#define NL     6

#define NCHUNK 64
#define CLEN   (SEQLEN / NCHUNK)   // 128

// ---------------- scratch (static device globals; no cudaMalloc allowed) ----
__device__ float g_X [SEQLEN * DM];
__device__ float g_HG[SEQLEN * 2 * DIN];
__device__ float g_HE[SEQLEN * DIN];
__device__ float g_FF[SEQLEN * DFF];
__device__ float g_rs[SEQLEN];
__device__ float g_chC [NCHUNK * DIN];
__device__ float g_chV [NCHUNK * DIN];
__device__ float g_hpre[NCHUNK * DIN];

// ---------------- TF32 GEMM: C[M,N] = op(A)[M,K] @ B[K,N] (+epilogue) ------
// Block tile 128x128x32, 256 threads (8 warps as 4m x 2n), warp tile 32x64,
// mma.sync.m16n8k8.tf32, double-buffered smem, pad strides chosen so all
// fragment LDS are bank-conflict-free:
//   sA stride 36: bank(r, c) = (36r + c) % 32 = (4r + c) % 32; A-frag fixes c,
//     varies r over 8 rows x 4 c-lanes -> bijective over 32 banks.
//   sB stride 136: bank(k, n) = (136k + n) % 32 = (8k + n) % 32; B-frag varies
//     k over 4 x 8 n-lanes -> bijective over 32 banks.
// FUSE=1: A element is scaled by rs[row] * (gamma[kcol] + 1) at smem store
// (fused rmsnorm; rs precomputed per row).
// STREAM=1: C stored with .cs (evict-first) — output never re-read (logits).
#define BM 128
#define BN 128
#define BK 32
#define SASTR 36
#define SBSTR 136
#define SMEM_FLOATS (2 * BM * SASTR + 2 * BK * SBSTR)
#define SMEM_BYTES  (SMEM_FLOATS * 4)

__device__ __forceinline__ float to_tf32(float x) {
    float r;
    asm("cvt.rna.tf32.f32 %0, %1;" : "=f"(r) : "f"(x));
    return r;
}

// EPI: 0 = none, 1 = +res, 2 = +bias then exact GELU, 3 = +bias +res
template <int EPI, int FUSE, int STREAM>
__global__ void __launch_bounds__(256, 1) gemm_kernel(
    const float* __restrict__ A, const float* __restrict__ B,
    const float* __restrict__ bias, const float* __restrict__ res,
    const float* __restrict__ rs, const float* __restrict__ gamma,
    float* __restrict__ C, int M, int N, int K)
{
    extern __shared__ float sm[];
    float* sA = sm;                    // [2][BM][SASTR]
    float* sB = sm + 2 * BM * SASTR;   // [2][BK][SBSTR]

    const int tid  = threadIdx.x;
    const int lane = tid & 31;
    const int warp = tid >> 5;
    const int wm   = warp >> 1;   // 0..3
    const int wn   = warp & 1;    // 0..1
    const int qr   = lane >> 2;   // 0..7
    const int qc   = lane & 3;    // 0..3

    const int m0 = blockIdx.y * BM;
    const int n0 = blockIdx.x * BN;

    // global->smem load mapping (tile dims divide exactly: no guards needed)
    const int a_r = tid >> 3;         // 0..31  (A rows, step 32)
    const int a_c = (tid & 7) * 4;    // 0..28  (A k-cols, float4)
    const int b_r = tid >> 5;         // 0..7   (B k-rows, step 8)
    const int b_c = (tid & 31) * 4;   // 0..124 (B n-cols, float4)

    // per-row norm scales for this thread's 4 A rows (constant over k)
    float rsv[4];
    if (FUSE) {
#pragma unroll
        for (int i = 0; i < 4; i++) rsv[i] = rs[m0 + a_r + 32 * i];
    }

    float4 ra[4], rb[4];
    float4 gv;                         // gamma+1 for this thread's 4 k-cols
    const int KT = K / BK;

    // ---- prologue: tile 0 -> buf 0 ----
#pragma unroll
    for (int i = 0; i < 4; i++)
        ra[i] = *reinterpret_cast<const float4*>(A + (size_t)(m0 + a_r + 32 * i) * K + a_c);
#pragma unroll
    for (int i = 0; i < 4; i++)
        rb[i] = *reinterpret_cast<const float4*>(B + (size_t)(b_r + 8 * i) * N + n0 + b_c);
    if (FUSE) {
        const float4 g = *reinterpret_cast<const float4*>(gamma + a_c);
        gv = make_float4(g.x + 1.f, g.y + 1.f, g.z + 1.f, g.w + 1.f);
    }
#pragma unroll
    for (int i = 0; i < 4; i++) {
        float* d = sA + (a_r + 32 * i) * SASTR + a_c;
        if (FUSE) {
            d[0] = to_tf32(ra[i].x * rsv[i] * gv.x);
            d[1] = to_tf32(ra[i].y * rsv[i] * gv.y);
            d[2] = to_tf32(ra[i].z * rsv[i] * gv.z);
            d[3] = to_tf32(ra[i].w * rsv[i] * gv.w);
        } else {
            d[0] = to_tf32(ra[i].x); d[1] = to_tf32(ra[i].y);
            d[2] = to_tf32(ra[i].z); d[3] = to_tf32(ra[i].w);
        }
    }
#pragma unroll
    for (int i = 0; i < 4; i++) {
        float* d = sB + (b_r + 8 * i) * SBSTR + b_c;
        d[0] = to_tf32(rb[i].x); d[1] = to_tf32(rb[i].y);
        d[2] = to_tf32(rb[i].z); d[3] = to_tf32(rb[i].w);
    }
    __syncthreads();

    float acc[2][8][4];
#pragma unroll
    for (int i = 0; i < 2; i++)
#pragma unroll
        for (int j = 0; j < 8; j++)
#pragma unroll
            for (int k = 0; k < 4; k++) acc[i][j][k] = 0.f;

    for (int kt = 0; kt < KT; ++kt) {
        if (kt + 1 < KT) {
#pragma unroll
            for (int i = 0; i < 4; i++)
                ra[i] = *reinterpret_cast<const float4*>(
                    A + (size_t)(m0 + a_r + 32 * i) * K + (kt + 1) * BK + a_c);
#pragma unroll
            for (int i = 0; i < 4; i++)
                rb[i] = *reinterpret_cast<const float4*>(
                    B + (size_t)((kt + 1) * BK + b_r + 8 * i) * N + n0 + b_c);
            if (FUSE) {
                const float4 g = *reinterpret_cast<const float4*>(
                    gamma + (kt + 1) * BK + a_c);
                gv = make_float4(g.x + 1.f, g.y + 1.f, g.z + 1.f, g.w + 1.f);
            }
        }
        const float* cA = sA + (kt & 1) * BM * SASTR;
        const float* cB = sB + (kt & 1) * BK * SBSTR;
#pragma unroll
        for (int ks = 0; ks < 4; ++ks) {
            const int kk = ks * 8;
            unsigned af[2][4];
            unsigned bf[8][2];
#pragma unroll
            for (int mt = 0; mt < 2; ++mt) {
                const float* p = cA + (wm * 32 + mt * 16 + qr) * SASTR + kk + qc;
                af[mt][0] = __float_as_uint(p[0]);
                af[mt][1] = __float_as_uint(p[8 * SASTR]);
                af[mt][2] = __float_as_uint(p[4]);
                af[mt][3] = __float_as_uint(p[8 * SASTR + 4]);
            }
#pragma unroll
            for (int nt = 0; nt < 8; ++nt) {
                const float* p = cB + (kk + qc) * SBSTR + wn * 64 + nt * 8 + qr;
                bf[nt][0] = __float_as_uint(p[0]);
                bf[nt][1] = __float_as_uint(p[4 * SBSTR]);
            }
#pragma unroll
            for (int mt = 0; mt < 2; ++mt)
#pragma unroll
                for (int nt = 0; nt < 8; ++nt)
                    asm volatile(
                        "mma.sync.aligned.m16n8k8.row.col.f32.tf32.tf32.f32 "
                        "{%0,%1,%2,%3}, {%4,%5,%6,%7}, {%8,%9}, {%0,%1,%2,%3};\n"
                        : "+f"(acc[mt][nt][0]), "+f"(acc[mt][nt][1]),
                          "+f"(acc[mt][nt][2]), "+f"(acc[mt][nt][3])
                        : "r"(af[mt][0]), "r"(af[mt][1]),
                          "r"(af[mt][2]), "r"(af[mt][3]),
                          "r"(bf[nt][0]), "r"(bf[nt][1]));
        }
        if (kt + 1 < KT) {
            float* dA = sA + ((kt + 1) & 1) * BM * SASTR;
            float* dB = sB + ((kt + 1) & 1) * BK * SBSTR;
#pragma unroll
            for (int i = 0; i < 4; i++) {
                float* d = dA + (a_r + 32 * i) * SASTR + a_c;
                if (FUSE) {
                    d[0] = to_tf32(ra[i].x * rsv[i] * gv.x);
                    d[1] = to_tf32(ra[i].y * rsv[i] * gv.y);
                    d[2] = to_tf32(ra[i].z * rsv[i] * gv.z);
                    d[3] = to_tf32(ra[i].w * rsv[i] * gv.w);
                } else {
                    d[0] = to_tf32(ra[i].x); d[1] = to_tf32(ra[i].y);
                    d[2] = to_tf32(ra[i].z); d[3] = to_tf32(ra[i].w);
                }
            }
#pragma unroll
            for (int i = 0; i < 4; i++) {
                float* d = dB + (b_r + 8 * i) * SBSTR + b_c;
                d[0] = to_tf32(rb[i].x); d[1] = to_tf32(rb[i].y);
                d[2] = to_tf32(rb[i].z); d[3] = to_tf32(rb[i].w);
            }
            __syncthreads();
        }
    }

    // ---- epilogue ----
    // Each lane-group (fixed qr) writes 32B contiguous spans: sector-granular
    // DRAM efficiency is 100%, no smem restage needed.
#pragma unroll
    for (int mt = 0; mt < 2; ++mt) {
#pragma unroll
        for (int nt = 0; nt < 8; ++nt) {
            const int row = m0 + wm * 32 + mt * 16 + qr;
            const int col = n0 + wn * 64 + nt * 8 + qc * 2;
#pragma unroll
            for (int h = 0; h < 2; ++h) {
                const int r = row + h * 8;
                const size_t off = (size_t)r * N + col;
                float v0 = acc[mt][nt][h * 2 + 0];
                float v1 = acc[mt][nt][h * 2 + 1];
                if (EPI == 1) {
                    v0 += res[off]; v1 += res[off + 1];
                } else if (EPI == 2) {
                    v0 += bias[col]; v1 += bias[col + 1];
                    v0 = 0.5f * v0 * (1.f + erff(v0 * 0.7071067811865476f));
                    v1 = 0.5f * v1 * (1.f + erff(v1 * 0.7071067811865476f));
                } else if (EPI == 3) {
                    v0 += bias[col] + res[off];
                    v1 += bias[col + 1] + res[off + 1];
                }
                if (STREAM) {
                    asm volatile("st.global.cs.v2.f32 [%0], {%1, %2};"
                                 :: "l"(C + off), "f"(v0), "f"(v1) : "memory");
                } else {
                    *reinterpret_cast<float2*>(C + off) = make_float2(v0, v1);
                }
            }
        }
    }
}

// ---------------- embedding gather ----------------
__global__ void embed_kernel(const int* __restrict__ tok,
                             const float* __restrict__ emb,
                             float* __restrict__ X)
{
    const int s = blockIdx.x;
    const int t = tok[s];
    const float4* e = reinterpret_cast<const float4*>(emb + (size_t)t * DM);
    float4* o = reinterpret_cast<float4*>(X + (size_t)s * DM);
    o[threadIdx.x] = e[threadIdx.x];   // 192 threads * float4 = 768
}

// ---------------- per-row norm scale: rs[m] = sqrt(768) / max(||x_m||,eps) --
__global__ void rowscale_kernel(const float* __restrict__ X,
                                float* __restrict__ rs)
{
    const int row = blockIdx.x;
    const float* x = X + (size_t)row * DM;
    const float v0 = x[threadIdx.x];
    const float v1 = x[threadIdx.x + 256];
    const float v2 = x[threadIdx.x + 512];
    float ss = v0 * v0 + v1 * v1 + v2 * v2;
#pragma unroll
    for (int o = 16; o > 0; o >>= 1) ss += __shfl_xor_sync(0xffffffffu, ss, o);
    __shared__ float red[8];
    if ((threadIdx.x & 31) == 0) red[threadIdx.x >> 5] = ss;
    __syncthreads();
    if (threadIdx.x == 0) {
        const float tot = red[0] + red[1] + red[2] + red[3] +
                          red[4] + red[5] + red[6] + red[7];
        rs[row] = 27.712812921102035f / fmaxf(sqrtf(tot), 1e-12f);
    }
}

// ---------------- gate math (recomputed in each scan pass) ----------------
// coeff c = sigmoid(-gate) = 1/(1+e^gate)  [= exp(-softplus(gate))]
// value v = sigmoid(gate) * g(hidden) = (1-c) * g(hidden)
// g(h) = h + 0.5 for h >= 0, sigmoid(h) otherwise
__device__ __forceinline__ void gate_cv(const float hid, const float gate,
                                        float& c, float& v)
{
    c = 1.f / (1.f + expf(gate));
    const float g = (hid >= 0.f) ? (hid + 0.5f) : 1.f / (1.f + expf(-hid));
    v = (1.f - c) * g;
}

// ---------------- 3-pass chunked linear scan: h_t = c_t*h_{t-1} + v_t -------
// Pass 1: per-chunk reduction (c-product, folded v). cv fused from HG.
// Normal loads: leave HG resident in L2 for pass 3.
__global__ void scan1_kernel(const float* __restrict__ HG,
                             float* __restrict__ chC, float* __restrict__ chV)
{
    const int j  = blockIdx.x * 128 + threadIdx.x;
    const int ch = blockIdx.y;
    const size_t base = (size_t)ch * CLEN * (2 * DIN) + j;
    float Ca = 1.f, Va = 0.f;
#pragma unroll 4
    for (int s = 0; s < CLEN; s++) {
        const float hid  = HG[base + (size_t)s * (2 * DIN)];
        const float gate = HG[base + (size_t)s * (2 * DIN) + DIN];
        float c, v;
        gate_cv(hid, gate, c, v);
        Ca *= c;
        Va = fmaf(c, Va, v);
    }
    chC[ch * DIN + j] = Ca;
    chV[ch * DIN + j] = Va;
}

// Pass 2: serial scan over the 64 chunk summaries (tiny).
__global__ void scan2_kernel(const float* __restrict__ chC,
                             const float* __restrict__ chV,
                             float* __restrict__ hpre)
{
    const int j = blockIdx.x * 128 + threadIdx.x;
    float h = 0.f;
#pragma unroll
    for (int i = 0; i < NCHUNK; i++) {
        hpre[i * DIN + j] = h;
        h = fmaf(chC[i * DIN + j], h, chV[i * DIN + j]);
    }
}

// Pass 3: re-expand within chunks with the carried-in prefix. cv fused.
// __ldcs: last use of HG -> evict-first, keep L2 for X/FF reuse.
__global__ void scan3_kernel(const float* __restrict__ HG,
                             const float* __restrict__ hpre,
                             float* __restrict__ H)
{
    const int j  = blockIdx.x * 128 + threadIdx.x;
    const int ch = blockIdx.y;
    const size_t base  = (size_t)ch * CLEN * (2 * DIN) + j;
    const size_t obase = (size_t)ch * CLEN * DIN + j;
    float h = hpre[ch * DIN + j];
#pragma unroll 4
    for (int s = 0; s < CLEN; s++) {
        const float hid  = __ldcs(HG + base + (size_t)s * (2 * DIN));
        const float gate = __ldcs(HG + base + (size_t)s * (2 * DIN) + DIN);
        float c, v;
        gate_cv(hid, gate, c, v);
        h = fmaf(c, h, v);
        H[obase + (size_t)s * DIN] = h;
    }
}

// ---------------- host side ----------------
template <int EPI, int FUSE, int STREAM>
static void launch_gemm(const float* A, const float* B, const float* bias,
                        const float* res, const float* rs, const float* gamma,
                        float* C, int M, int N, int K)
{
    cudaFuncSetAttribute(gemm_kernel<EPI, FUSE, STREAM>,
                         cudaFuncAttributeMaxDynamicSharedMemorySize, SMEM_BYTES);
    dim3 grid(N / BN, M / BM);
    gemm_kernel<EPI, FUSE, STREAM><<<grid, 256, SMEM_BYTES>>>(
        A, B, bias, res, rs, gamma, C, M, N, K);
}

extern "C" void kernel_launch(void* const* d_in, const int* in_sizes, int n_in,
                              void* d_out, int out_size)
{
    const int*   tokens   = (const int*)  d_in[0];
    const float* emb      = (const float*)d_in[1];
    const float* gamma1   = (const float*)d_in[2];
    const float* W_hg     = (const float*)d_in[3];
    const float* W_out    = (const float*)d_in[4];
    const float* gamma2   = (const float*)d_in[5];
    const float* W_ff1    = (const float*)d_in[6];
    const float* b_ff1    = (const float*)d_in[7];
    const float* W_ff2    = (const float*)d_in[8];
    const float* b_ff2    = (const float*)d_in[9];
    const float* gamma_f  = (const float*)d_in[10];
    const float* W_logits = (const float*)d_in[11];
    float* out = (float*)d_out;

    float *X, *HG, *HE, *FF, *rs, *chC, *chV, *hpre;
    cudaGetSymbolAddress((void**)&X,    g_X);
    cudaGetSymbolAddress((void**)&HG,   g_HG);
    cudaGetSymbolAddress((void**)&HE,   g_HE);
    cudaGetSymbolAddress((void**)&FF,   g_FF);
    cudaGetSymbolAddress((void**)&rs,   g_rs);
    cudaGetSymbolAddress((void**)&chC,  g_chC);
    cudaGetSymbolAddress((void**)&chV,  g_chV);
    cudaGetSymbolAddress((void**)&hpre, g_hpre);

    embed_kernel<<<SEQLEN, 192>>>(tokens, emb, X);

    for (int l = 0; l < NL; ++l) {
        // pre-norm 1 fused into the W_hg GEMM
        rowscale_kernel<<<SEQLEN, 256>>>(X, rs);
        launch_gemm<0, 1, 0>(X, W_hg + (size_t)l * DM * 2 * DIN,
                             nullptr, nullptr, rs, gamma1 + (size_t)l * DM,
                             HG, SEQLEN, 2 * DIN, DM);

        scan1_kernel<<<dim3(DIN / 128, NCHUNK), 128>>>(HG, chC, chV);
        scan2_kernel<<<DIN / 128, 128>>>(chC, chV, hpre);
        scan3_kernel<<<dim3(DIN / 128, NCHUNK), 128>>>(HG, hpre, HE);

        launch_gemm<1, 0, 0>(HE, W_out + (size_t)l * DIN * DM,
                             nullptr, X, nullptr, nullptr, X, SEQLEN, DM, DIN);

        // pre-norm 2 fused into the FF1 GEMM
        rowscale_kernel<<<SEQLEN, 256>>>(X, rs);
        launch_gemm<2, 1, 0>(X, W_ff1 + (size_t)l * DM * DFF,
                             b_ff1 + (size_t)l * DFF, nullptr,
                             rs, gamma2 + (size_t)l * DM, FF, SEQLEN, DFF, DM);

        launch_gemm<3, 0, 0>(FF, W_ff2 + (size_t)l * DFF * DM,
                             b_ff2 + (size_t)l * DM, X, nullptr, nullptr,
                             X, SEQLEN, DM, DFF);
    }

    // final norm fused into the logits GEMM (streaming store: output is dead)
    rowscale_kernel<<<SEQLEN, 256>>>(X, rs);
    launch_gemm<0, 1, 1>(X, W_logits, nullptr, nullptr, rs, gamma_f,
                         out, SEQLEN, VOC, DM);
}

// round 12
// speedup vs baseline: 1.0601x; 1.0601x over previous
#include <cuda_runtime.h>
#include <cstdint>
#include <cstddef>

// ---------------- problem constants ----------------
#define SEQLEN 8192
#define DM     768
#define DIN    1152     // 1.5 * 768
#define DFF    3072     // 4 * 768
#define VOC    32000
#define NL     6

#define NCHUNK 256
#define CLEN   (SEQLEN / NCHUNK)   // 32

// ---------------- scratch (static device globals; no cudaMalloc allowed) ----
__device__ float g_X [SEQLEN * DM];
__device__ float g_HG[SEQLEN * 2 * DIN];
__device__ float g_HE[SEQLEN * DIN];
__device__ float g_FF[SEQLEN * DFF];
__device__ float g_rs[SEQLEN];
__device__ float g_chC [NCHUNK * DIN];
__device__ float g_chV [NCHUNK * DIN];
__device__ float g_hpre[NCHUNK * DIN];
__device__ int   g_dummy;

// ---------------- TF32 GEMM: C[M,N] = op(A)[M,K] @ B[K,N] (+epilogue) ------
// (tcgen05 is NOT available: harness compiles PTX at target sm_103, which
//  rejects all tcgen05.* — confirmed by R10 ptxas errors. mma.sync is the
//  only tensor path; R4 measured it at ~117 TF/s effective.)
// Block tile 128x128x32, 256 threads (8 warps as 4m x 2n), warp tile 32x64,
// mma.sync.m16n8k8.tf32, double-buffered smem, pad strides chosen so all
// fragment LDS are bank-conflict-free:
//   sA stride 36: bank(r, c) = (4r + c) % 32 -> bijective over fragment lanes.
//   sB stride 136: bank(k, n) = (8k + n) % 32 -> bijective over fragment lanes.
// FUSE=1: A scaled by rs[row] * (gamma[kcol] + 1) at smem store (fused rmsnorm).
// STREAM=1: C stored with .cs (evict-first) — output never re-read (logits).
#define BM 128
#define BN 128
#define BK 32
#define SASTR 36
#define SBSTR 136
#define SMEM_FLOATS (2 * BM * SASTR + 2 * BK * SBSTR)
#define SMEM_BYTES  (SMEM_FLOATS * 4)

__device__ __forceinline__ float to_tf32(float x) {
    float r;
    asm("cvt.rna.tf32.f32 %0, %1;" : "=f"(r) : "f"(x));
    return r;
}

// EPI: 0 = none, 1 = +res, 2 = +bias then exact GELU, 3 = +bias +res
template <int EPI, int FUSE, int STREAM>
__global__ void __launch_bounds__(256, 1) gemm_kernel(
    const float* __restrict__ A, const float* __restrict__ B,
    const float* __restrict__ bias, const float* __restrict__ res,
    const float* __restrict__ rs, const float* __restrict__ gamma,
    float* __restrict__ C, int M, int N, int K)
{
    extern __shared__ float sm[];
    float* sA = sm;                    // [2][BM][SASTR]
    float* sB = sm + 2 * BM * SASTR;   // [2][BK][SBSTR]

    const int tid  = threadIdx.x;
    const int lane = tid & 31;
    const int warp = tid >> 5;
    const int wm   = warp >> 1;   // 0..3
    const int wn   = warp & 1;    // 0..1
    const int qr   = lane >> 2;   // 0..7
    const int qc   = lane & 3;    // 0..3

    const int m0 = blockIdx.y * BM;
    const int n0 = blockIdx.x * BN;

    const int a_r = tid >> 3;         // 0..31  (A rows, step 32)
    const int a_c = (tid & 7) * 4;    // 0..28  (A k-cols, float4)
    const int b_r = tid >> 5;         // 0..7   (B k-rows, step 8)
    const int b_c = (tid & 31) * 4;   // 0..124 (B n-cols, float4)

    float rsv[4];
    if (FUSE) {
#pragma unroll
        for (int i = 0; i < 4; i++) rsv[i] = rs[m0 + a_r + 32 * i];
    }

    float4 ra[4], rb[4];
    float4 gv;
    const int KT = K / BK;

    // ---- prologue: tile 0 -> buf 0 ----
#pragma unroll
    for (int i = 0; i < 4; i++)
        ra[i] = *reinterpret_cast<const float4*>(A + (size_t)(m0 + a_r + 32 * i) * K + a_c);
#pragma unroll
    for (int i = 0; i < 4; i++)
        rb[i] = *reinterpret_cast<const float4*>(B + (size_t)(b_r + 8 * i) * N + n0 + b_c);
    if (FUSE) {
        const float4 g = *reinterpret_cast<const float4*>(gamma + a_c);
        gv = make_float4(g.x + 1.f, g.y + 1.f, g.z + 1.f, g.w + 1.f);
    }
#pragma unroll
    for (int i = 0; i < 4; i++) {
        float* d = sA + (a_r + 32 * i) * SASTR + a_c;
        if (FUSE) {
            d[0] = to_tf32(ra[i].x * rsv[i] * gv.x);
            d[1] = to_tf32(ra[i].y * rsv[i] * gv.y);
            d[2] = to_tf32(ra[i].z * rsv[i] * gv.z);
            d[3] = to_tf32(ra[i].w * rsv[i] * gv.w);
        } else {
            d[0] = to_tf32(ra[i].x); d[1] = to_tf32(ra[i].y);
            d[2] = to_tf32(ra[i].z); d[3] = to_tf32(ra[i].w);
        }
    }
#pragma unroll
    for (int i = 0; i < 4; i++) {
        float* d = sB + (b_r + 8 * i) * SBSTR + b_c;
        d[0] = to_tf32(rb[i].x); d[1] = to_tf32(rb[i].y);
        d[2] = to_tf32(rb[i].z); d[3] = to_tf32(rb[i].w);
    }
    __syncthreads();

    float acc[2][8][4];
#pragma unroll
    for (int i = 0; i < 2; i++)
#pragma unroll
        for (int j = 0; j < 8; j++)
#pragma unroll
            for (int k = 0; k < 4; k++) acc[i][j][k] = 0.f;

    for (int kt = 0; kt < KT; ++kt) {
        if (kt + 1 < KT) {
#pragma unroll
            for (int i = 0; i < 4; i++)
                ra[i] = *reinterpret_cast<const float4*>(
                    A + (size_t)(m0 + a_r + 32 * i) * K + (kt + 1) * BK + a_c);
#pragma unroll
            for (int i = 0; i < 4; i++)
                rb[i] = *reinterpret_cast<const float4*>(
                    B + (size_t)((kt + 1) * BK + b_r + 8 * i) * N + n0 + b_c);
            if (FUSE) {
                const float4 g = *reinterpret_cast<const float4*>(
                    gamma + (kt + 1) * BK + a_c);
                gv = make_float4(g.x + 1.f, g.y + 1.f, g.z + 1.f, g.w + 1.f);
            }
        }
        const float* cA = sA + (kt & 1) * BM * SASTR;
        const float* cB = sB + (kt & 1) * BK * SBSTR;
#pragma unroll
        for (int ks = 0; ks < 4; ++ks) {
            const int kk = ks * 8;
            unsigned af[2][4];
            unsigned bf[8][2];
#pragma unroll
            for (int mt = 0; mt < 2; ++mt) {
                const float* p = cA + (wm * 32 + mt * 16 + qr) * SASTR + kk + qc;
                af[mt][0] = __float_as_uint(p[0]);
                af[mt][1] = __float_as_uint(p[8 * SASTR]);
                af[mt][2] = __float_as_uint(p[4]);
                af[mt][3] = __float_as_uint(p[8 * SASTR + 4]);
            }
#pragma unroll
            for (int nt = 0; nt < 8; ++nt) {
                const float* p = cB + (kk + qc) * SBSTR + wn * 64 + nt * 8 + qr;
                bf[nt][0] = __float_as_uint(p[0]);
                bf[nt][1] = __float_as_uint(p[4 * SBSTR]);
            }
#pragma unroll
            for (int mt = 0; mt < 2; ++mt)
#pragma unroll
                for (int nt = 0; nt < 8; ++nt)
                    asm volatile(
                        "mma.sync.aligned.m16n8k8.row.col.f32.tf32.tf32.f32 "
                        "{%0,%1,%2,%3}, {%4,%5,%6,%7}, {%8,%9}, {%0,%1,%2,%3};\n"
                        : "+f"(acc[mt][nt][0]), "+f"(acc[mt][nt][1]),
                          "+f"(acc[mt][nt][2]), "+f"(acc[mt][nt][3])
                        : "r"(af[mt][0]), "r"(af[mt][1]),
                          "r"(af[mt][2]), "r"(af[mt][3]),
                          "r"(bf[nt][0]), "r"(bf[nt][1]));
        }
        if (kt + 1 < KT) {
            float* dA = sA + ((kt + 1) & 1) * BM * SASTR;
            float* dB = sB + ((kt + 1) & 1) * BK * SBSTR;
#pragma unroll
            for (int i = 0; i < 4; i++) {
                float* d = dA + (a_r + 32 * i) * SASTR + a_c;
                if (FUSE) {
                    d[0] = to_tf32(ra[i].x * rsv[i] * gv.x);
                    d[1] = to_tf32(ra[i].y * rsv[i] * gv.y);
                    d[2] = to_tf32(ra[i].z * rsv[i] * gv.z);
                    d[3] = to_tf32(ra[i].w * rsv[i] * gv.w);
                } else {
                    d[0] = to_tf32(ra[i].x); d[1] = to_tf32(ra[i].y);
                    d[2] = to_tf32(ra[i].z); d[3] = to_tf32(ra[i].w);
                }
            }
#pragma unroll
            for (int i = 0; i < 4; i++) {
                float* d = dB + (b_r + 8 * i) * SBSTR + b_c;
                d[0] = to_tf32(rb[i].x); d[1] = to_tf32(rb[i].y);
                d[2] = to_tf32(rb[i].z); d[3] = to_tf32(rb[i].w);
            }
            __syncthreads();
        }
    }

    // ---- epilogue ----
#pragma unroll
    for (int mt = 0; mt < 2; ++mt) {
#pragma unroll
        for (int nt = 0; nt < 8; ++nt) {
            const int row = m0 + wm * 32 + mt * 16 + qr;
            const int col = n0 + wn * 64 + nt * 8 + qc * 2;
#pragma unroll
            for (int h = 0; h < 2; ++h) {
                const int r = row + h * 8;
                const size_t off = (size_t)r * N + col;
                float v0 = acc[mt][nt][h * 2 + 0];
                float v1 = acc[mt][nt][h * 2 + 1];
                if (EPI == 1) {
                    v0 += res[off]; v1 += res[off + 1];
                } else if (EPI == 2) {
                    v0 += bias[col]; v1 += bias[col + 1];
                    v0 = 0.5f * v0 * (1.f + erff(v0 * 0.7071067811865476f));
                    v1 = 0.5f * v1 * (1.f + erff(v1 * 0.7071067811865476f));
                } else if (EPI == 3) {
                    v0 += bias[col] + res[off];
                    v1 += bias[col + 1] + res[off + 1];
                }
                if (STREAM) {
                    asm volatile("st.global.cs.v2.f32 [%0], {%1, %2};"
                                 :: "l"(C + off), "f"(v0), "f"(v1) : "memory");
                } else {
                    *reinterpret_cast<float2*>(C + off) = make_float2(v0, v1);
                }
            }
        }
    }
}

// ---------------- ncu-alignment dummy (profiler captures launch #6) --------
__global__ void dummy_kernel(int* d) { if (threadIdx.x == 1024) *d = 0; }

// ---------------- embedding gather ----------------
__global__ void embed_kernel(const int* __restrict__ tok,
                             const float* __restrict__ emb,
                             float* __restrict__ X)
{
    const int s = blockIdx.x;
    const int t = tok[s];
    const float4* e = reinterpret_cast<const float4*>(emb + (size_t)t * DM);
    float4* o = reinterpret_cast<float4*>(X + (size_t)s * DM);
    o[threadIdx.x] = e[threadIdx.x];   // 192 threads * float4 = 768
}

// ---------------- per-row norm scale: rs[m] = sqrt(768)/max(||x_m||,eps) ---
__global__ void rowscale_kernel(const float* __restrict__ X,
                                float* __restrict__ rs)
{
    const int row = blockIdx.x;
    const float* x = X + (size_t)row * DM;
    const float v0 = x[threadIdx.x];
    const float v1 = x[threadIdx.x + 256];
    const float v2 = x[threadIdx.x + 512];
    float ss = v0 * v0 + v1 * v1 + v2 * v2;
#pragma unroll
    for (int o = 16; o > 0; o >>= 1) ss += __shfl_xor_sync(0xffffffffu, ss, o);
    __shared__ float red[8];
    if ((threadIdx.x & 31) == 0) red[threadIdx.x >> 5] = ss;
    __syncthreads();
    if (threadIdx.x == 0) {
        const float tot = red[0] + red[1] + red[2] + red[3] +
                          red[4] + red[5] + red[6] + red[7];
        rs[row] = 27.712812921102035f / fmaxf(sqrtf(tot), 1e-12f);
    }
}

// ---------------- gate math (recomputed in each scan pass) ----------------
__device__ __forceinline__ void gate_cv(const float hid, const float gate,
                                        float& c, float& v)
{
    c = 1.f / (1.f + expf(gate));
    const float g = (hid >= 0.f) ? (hid + 0.5f) : 1.f / (1.f + expf(-hid));
    v = (1.f - c) * g;
}

// ---------------- 3-pass chunked linear scan: h_t = c_t*h_{t-1} + v_t ------
// NCHUNK=256 -> 2304 blocks (~97% occupancy vs 23% measured at NCHUNK=64).
__global__ void scan1_kernel(const float* __restrict__ HG,
                             float* __restrict__ chC, float* __restrict__ chV)
{
    const int j  = blockIdx.x * 128 + threadIdx.x;
    const int ch = blockIdx.y;
    const size_t base = (size_t)ch * CLEN * (2 * DIN) + j;
    float Ca = 1.f, Va = 0.f;
#pragma unroll 4
    for (int s = 0; s < CLEN; s++) {
        const float hid  = HG[base + (size_t)s * (2 * DIN)];
        const float gate = HG[base + (size_t)s * (2 * DIN) + DIN];
        float c, v;
        gate_cv(hid, gate, c, v);
        Ca *= c;
        Va = fmaf(c, Va, v);
    }
    chC[ch * DIN + j] = Ca;
    chV[ch * DIN + j] = Va;
}

__global__ void scan2_kernel(const float* __restrict__ chC,
                             const float* __restrict__ chV,
                             float* __restrict__ hpre)
{
    const int j = blockIdx.x * 128 + threadIdx.x;
    float h = 0.f;
#pragma unroll 8
    for (int i = 0; i < NCHUNK; i++) {
        hpre[i * DIN + j] = h;
        h = fmaf(chC[i * DIN + j], h, chV[i * DIN + j]);
    }
}

__global__ void scan3_kernel(const float* __restrict__ HG,
                             const float* __restrict__ hpre,
                             float* __restrict__ H)
{
    const int j  = blockIdx.x * 128 + threadIdx.x;
    const int ch = blockIdx.y;
    const size_t base  = (size_t)ch * CLEN * (2 * DIN) + j;
    const size_t obase = (size_t)ch * CLEN * DIN + j;
    float h = hpre[ch * DIN + j];
#pragma unroll 4
    for (int s = 0; s < CLEN; s++) {
        const float hid  = __ldcs(HG + base + (size_t)s * (2 * DIN));
        const float gate = __ldcs(HG + base + (size_t)s * (2 * DIN) + DIN);
        float c, v;
        gate_cv(hid, gate, c, v);
        h = fmaf(c, h, v);
        H[obase + (size_t)s * DIN] = h;
    }
}

// ---------------- host side ----------------
template <int EPI, int FUSE, int STREAM>
static void launch_gemm(const float* A, const float* B, const float* bias,
                        const float* res, const float* rs, const float* gamma,
                        float* C, int M, int N, int K)
{
    cudaFuncSetAttribute(gemm_kernel<EPI, FUSE, STREAM>,
                         cudaFuncAttributeMaxDynamicSharedMemorySize, SMEM_BYTES);
    dim3 grid(N / BN, M / BM);
    gemm_kernel<EPI, FUSE, STREAM><<<grid, 256, SMEM_BYTES>>>(
        A, B, bias, res, rs, gamma, C, M, N, K);
}

extern "C" void kernel_launch(void* const* d_in, const int* in_sizes, int n_in,
                              void* d_out, int out_size)
{
    const int*   tokens   = (const int*)  d_in[0];
    const float* emb      = (const float*)d_in[1];
    const float* gamma1   = (const float*)d_in[2];
    const float* W_hg     = (const float*)d_in[3];
    const float* W_out    = (const float*)d_in[4];
    const float* gamma2   = (const float*)d_in[5];
    const float* W_ff1    = (const float*)d_in[6];
    const float* b_ff1    = (const float*)d_in[7];
    const float* W_ff2    = (const float*)d_in[8];
    const float* b_ff2    = (const float*)d_in[9];
    const float* gamma_f  = (const float*)d_in[10];
    const float* W_logits = (const float*)d_in[11];
    float* out = (float*)d_out;

    float *X, *HG, *HE, *FF, *rs, *chC, *chV, *hpre;
    int* dm;
    cudaGetSymbolAddress((void**)&X,    g_X);
    cudaGetSymbolAddress((void**)&HG,   g_HG);
    cudaGetSymbolAddress((void**)&HE,   g_HE);
    cudaGetSymbolAddress((void**)&FF,   g_FF);
    cudaGetSymbolAddress((void**)&rs,   g_rs);
    cudaGetSymbolAddress((void**)&chC,  g_chC);
    cudaGetSymbolAddress((void**)&chV,  g_chV);
    cudaGetSymbolAddress((void**)&hpre, g_hpre);
    cudaGetSymbolAddress((void**)&dm,   g_dummy);

    // 3 dummies so ncu (-s 5 -c 1) captures launch #6 = first W_hg GEMM
    dummy_kernel<<<1, 32>>>(dm);
    dummy_kernel<<<1, 32>>>(dm);
    dummy_kernel<<<1, 32>>>(dm);

    embed_kernel<<<SEQLEN, 192>>>(tokens, emb, X);

    for (int l = 0; l < NL; ++l) {
        rowscale_kernel<<<SEQLEN, 256>>>(X, rs);
        launch_gemm<0, 1, 0>(X, W_hg + (size_t)l * DM * 2 * DIN,
                             nullptr, nullptr, rs, gamma1 + (size_t)l * DM,
                             HG, SEQLEN, 2 * DIN, DM);

        scan1_kernel<<<dim3(DIN / 128, NCHUNK), 128>>>(HG, chC, chV);
        scan2_kernel<<<DIN / 128, 128>>>(chC, chV, hpre);
        scan3_kernel<<<dim3(DIN / 128, NCHUNK), 128>>>(HG, hpre, HE);

        launch_gemm<1, 0, 0>(HE, W_out + (size_t)l * DIN * DM,
                             nullptr, X, nullptr, nullptr, X, SEQLEN, DM, DIN);

        rowscale_kernel<<<SEQLEN, 256>>>(X, rs);
        launch_gemm<2, 1, 0>(X, W_ff1 + (size_t)l * DM * DFF,
                             b_ff1 + (size_t)l * DFF, nullptr,
                             rs, gamma2 + (size_t)l * DM, FF, SEQLEN, DFF, DM);

        launch_gemm<3, 0, 0>(FF, W_ff2 + (size_t)l * DFF * DM,
                             b_ff2 + (size_t)l * DM, X, nullptr, nullptr,
                             X, SEQLEN, DM, DFF);
    }

    rowscale_kernel<<<SEQLEN, 256>>>(X, rs);
    launch_gemm<0, 1, 1>(X, W_logits, nullptr, nullptr, rs, gamma_f,
                         out, SEQLEN, VOC, DM);
}